// round 5
// baseline (speedup 1.0000x reference)
#include <cuda_runtime.h>

// CosineSim3D — persistent overlapped pipeline.
//   phase1 (200 CTAs): partial sums of normalized b rows  -> g_part4, fold -> g_s4
//   phase2 (200 CTAs): score a rows vs s_b -> g_scores; last item does softmax -> g_probs
//   phase3 (192 CTAs): broadcast-write probs to out
// Per-batch flags through L2 atomics; dynamic ticket queues per phase.
// grid = 592 = 148 SMs x 4 CTAs (all resident -> spin-safe).

#define BATCH   128
#define NROWS   1024
#define DIM     300
#define NF4     75
#define EPSV    1e-7f

#define THREADS 256
#define NP1     200
#define NP2     200
#define NP3     192
#define GRID    (NP1 + NP2 + NP3)     // 592

#define P1_ITEMS 1024                  // 8 per batch, 128 rows each
#define P2_ITEMS 1024                  // 8 per batch, 128 rows each
#define P3_ITEMS 2048                  // 16 per batch, 64 rows each

// scratch (no cudaMalloc allowed)
__device__ float4 g_part4[BATCH * 8 * NF4];
__device__ float4 g_s4[BATCH * NF4];
__device__ float  g_scores[BATCH * NROWS];
__device__ float  g_probs[BATCH * NROWS];
__device__ int    g_count1[BATCH];
__device__ int    g_count2[BATCH];
__device__ int    g_flag_s[BATCH];
__device__ int    g_flag_sm[BATCH];
__device__ int    g_ticket[4];

__device__ __forceinline__ float dot4(float4 x, float4 y) {
    return x.x * y.x + x.y * y.y + x.z * y.z + x.w * y.w;
}
__device__ __forceinline__ void fma4(float4& a, float4 v, float s) {
    a.x += v.x * s; a.y += v.y * s; a.z += v.z * s; a.w += v.w * s;
}
__device__ __forceinline__ void add4(float4& a, float4 v) {
    a.x += v.x; a.y += v.y; a.z += v.z; a.w += v.w;
}

__global__ void reset_kernel()
{
    const int i = threadIdx.x;
    if (i < BATCH) {
        g_count1[i] = 0; g_count2[i] = 0;
        g_flag_s[i] = 0; g_flag_sm[i] = 0;
    }
    if (i < 4) g_ticket[i] = 0;
}

__global__ __launch_bounds__(THREADS, 4) void persistent_kernel(
    const float* __restrict__ a, const float* __restrict__ b,
    float* __restrict__ out)
{
    __shared__ union {
        float4 sw4[8][NF4 + 1];   // phase1 cross-warp partials
        float  pr[64];            // phase3 probs slice
    } u;
    __shared__ int   sh_i;
    __shared__ int   sh_c;
    __shared__ float sh_red[8];
    __shared__ float sh_M, sh_S;

    const int bid  = blockIdx.x;
    const int tid  = threadIdx.x;
    const int warp = tid >> 5;
    const int lane = tid & 31;
    const float4 z4 = make_float4(0.f, 0.f, 0.f, 0.f);

    // =====================================================================
    if (bid < NP1) {                                    // ---- PHASE 1 ----
        for (;;) {
            __syncthreads();                            // protect u.sw4 / sh_i
            if (tid == 0) sh_i = atomicAdd(&g_ticket[0], 1);
            __syncthreads();
            const int item = sh_i;
            if (item >= P1_ITEMS) break;
            const int k = item >> 3, s = item & 7;

            const float4* b4 = reinterpret_cast<const float4*>(b)
                             + ((size_t)k * NROWS + s * 128) * NF4;

            float4 acc0 = z4, acc1 = z4, acc2 = z4;
#pragma unroll 2
            for (int i = 0; i < 8; i++) {               // 2 rows per iter
                const float4* rowA = b4 + (warp + 16 * i) * NF4;
                const float4* rowB = rowA + 8 * NF4;
                const float4 A0 = __ldcs(rowA + lane);
                const float4 A1 = __ldcs(rowA + lane + 32);
                const float4 B0 = __ldcs(rowB + lane);
                const float4 B1 = __ldcs(rowB + lane + 32);
                const float4 A2 = (lane < NF4 - 64) ? __ldcs(rowA + lane + 64) : z4;
                const float4 B2 = (lane < NF4 - 64) ? __ldcs(rowB + lane + 64) : z4;
                float sA = dot4(A0, A0) + dot4(A1, A1) + dot4(A2, A2);
                float sB = dot4(B0, B0) + dot4(B1, B1) + dot4(B2, B2);
#pragma unroll
                for (int o = 16; o > 0; o >>= 1) {
                    sA += __shfl_xor_sync(0xffffffffu, sA, o);
                    sB += __shfl_xor_sync(0xffffffffu, sB, o);
                }
                const float iA = rsqrtf(fmaxf(sA, EPSV));
                const float iB = rsqrtf(fmaxf(sB, EPSV));
                fma4(acc0, A0, iA); fma4(acc0, B0, iB);
                fma4(acc1, A1, iA); fma4(acc1, B1, iB);
                fma4(acc2, A2, iA); fma4(acc2, B2, iB);
            }
            u.sw4[warp][lane]      = acc0;
            u.sw4[warp][lane + 32] = acc1;
            if (lane < NF4 - 64) u.sw4[warp][lane + 64] = acc2;
            __syncthreads();

            if (tid < NF4) {
                float4 t = u.sw4[0][tid];
#pragma unroll
                for (int w = 1; w < 8; w++) add4(t, u.sw4[w][tid]);
                g_part4[(k * 8 + s) * NF4 + tid] = t;
            }
            __threadfence();
            __syncthreads();
            if (tid == 0) sh_c = atomicAdd(&g_count1[k], 1);
            __syncthreads();

            if (sh_c == 7) {                            // last sub: fold 8 -> s_b
                __threadfence();
                if (tid < NF4) {
                    float4 t = __ldcg(&g_part4[(k * 8 + 0) * NF4 + tid]);
#pragma unroll
                    for (int p = 1; p < 8; p++)
                        add4(t, __ldcg(&g_part4[(k * 8 + p) * NF4 + tid]));
                    g_s4[k * NF4 + tid] = t;
                }
                __threadfence();
                __syncthreads();
                if (tid == 0) atomicExch(&g_flag_s[k], 1);
            }
        }
    // =====================================================================
    } else if (bid < NP1 + NP2) {                       // ---- PHASE 2 ----
        for (;;) {
            __syncthreads();
            if (tid == 0) sh_i = atomicAdd(&g_ticket[1], 1);
            __syncthreads();
            const int item = sh_i;
            if (item >= P2_ITEMS) break;
            const int k = item >> 3, s = item & 7;

            if (tid == 0) {
                while (atomicAdd(&g_flag_s[k], 0) == 0) __nanosleep(200);
            }
            __syncthreads();
            __threadfence();

            const float4 s0 = __ldcg(&g_s4[k * NF4 + lane]);
            const float4 s1 = __ldcg(&g_s4[k * NF4 + lane + 32]);
            const float4 s2 = (lane < NF4 - 64) ? __ldcg(&g_s4[k * NF4 + lane + 64]) : z4;

            const float4* a4 = reinterpret_cast<const float4*>(a)
                             + ((size_t)k * NROWS + s * 128) * NF4;
            float* sc = g_scores + k * NROWS + s * 128;

#pragma unroll 2
            for (int i = 0; i < 8; i++) {
                const int rA = warp + 16 * i;
                const float4* rowA = a4 + rA * NF4;
                const float4* rowB = rowA + 8 * NF4;
                const float4 A0 = __ldcs(rowA + lane);
                const float4 A1 = __ldcs(rowA + lane + 32);
                const float4 B0 = __ldcs(rowB + lane);
                const float4 B1 = __ldcs(rowB + lane + 32);
                const float4 A2 = (lane < NF4 - 64) ? __ldcs(rowA + lane + 64) : z4;
                const float4 B2 = (lane < NF4 - 64) ? __ldcs(rowB + lane + 64) : z4;
                float dA = dot4(A0, s0) + dot4(A1, s1) + dot4(A2, s2);
                float nA = dot4(A0, A0) + dot4(A1, A1) + dot4(A2, A2);
                float dB = dot4(B0, s0) + dot4(B1, s1) + dot4(B2, s2);
                float nB = dot4(B0, B0) + dot4(B1, B1) + dot4(B2, B2);
#pragma unroll
                for (int o = 16; o > 0; o >>= 1) {
                    dA += __shfl_xor_sync(0xffffffffu, dA, o);
                    nA += __shfl_xor_sync(0xffffffffu, nA, o);
                    dB += __shfl_xor_sync(0xffffffffu, dB, o);
                    nB += __shfl_xor_sync(0xffffffffu, nB, o);
                }
                if (lane == 0) {
                    sc[rA]     = dA * rsqrtf(fmaxf(nA, EPSV));
                    sc[rA + 8] = dB * rsqrtf(fmaxf(nB, EPSV));
                }
            }
            __threadfence();
            __syncthreads();
            if (tid == 0) sh_c = atomicAdd(&g_count2[k], 1);
            __syncthreads();

            if (sh_c == 7) {                            // last sub: softmax
                __threadfence();
                const float x0 = __ldcg(&g_scores[k * NROWS + tid]);
                const float x1 = __ldcg(&g_scores[k * NROWS + tid + 256]);
                const float x2 = __ldcg(&g_scores[k * NROWS + tid + 512]);
                const float x3 = __ldcg(&g_scores[k * NROWS + tid + 768]);

                float m = fmaxf(fmaxf(x0, x1), fmaxf(x2, x3));
#pragma unroll
                for (int o = 16; o > 0; o >>= 1)
                    m = fmaxf(m, __shfl_xor_sync(0xffffffffu, m, o));
                if (lane == 0) sh_red[warp] = m;
                __syncthreads();
                if (warp == 0) {
                    float t = (lane < 8) ? sh_red[lane] : -3.4e38f;
#pragma unroll
                    for (int o = 4; o > 0; o >>= 1)
                        t = fmaxf(t, __shfl_xor_sync(0xffffffffu, t, o));
                    if (lane == 0) sh_M = t;
                }
                __syncthreads();
                const float M = sh_M;

                const float e0 = __expf(x0 - M);
                const float e1 = __expf(x1 - M);
                const float e2 = __expf(x2 - M);
                const float e3 = __expf(x3 - M);
                float sum = e0 + e1 + e2 + e3;
#pragma unroll
                for (int o = 16; o > 0; o >>= 1)
                    sum += __shfl_xor_sync(0xffffffffu, sum, o);
                if (lane == 0) sh_red[warp] = sum;
                __syncthreads();
                if (warp == 0) {
                    float t = (lane < 8) ? sh_red[lane] : 0.f;
#pragma unroll
                    for (int o = 4; o > 0; o >>= 1)
                        t += __shfl_xor_sync(0xffffffffu, t, o);
                    if (lane == 0) sh_S = t;
                }
                __syncthreads();
                const float inv = __frcp_rn(sh_S);

                g_probs[k * NROWS + tid]       = e0 * inv;
                g_probs[k * NROWS + tid + 256] = e1 * inv;
                g_probs[k * NROWS + tid + 512] = e2 * inv;
                g_probs[k * NROWS + tid + 768] = e3 * inv;
                __threadfence();
                __syncthreads();
                if (tid == 0) atomicExch(&g_flag_sm[k], 1);
            }
        }
    // =====================================================================
    } else {                                            // ---- PHASE 3 ----
        for (;;) {
            __syncthreads();                            // protect u.pr / sh_i
            if (tid == 0) sh_i = atomicAdd(&g_ticket[2], 1);
            __syncthreads();
            const int item = sh_i;
            if (item >= P3_ITEMS) break;
            const int k = item >> 4, s = item & 15;

            if (tid == 0) {
                while (atomicAdd(&g_flag_sm[k], 0) == 0) __nanosleep(200);
            }
            __syncthreads();
            if (tid < 64)
                u.pr[tid] = __ldcg(&g_probs[k * NROWS + s * 64 + tid]);
            __syncthreads();

            float4* o4 = reinterpret_cast<float4*>(out)
                       + ((size_t)k * NROWS + s * 64) * NF4;
#pragma unroll 4
            for (int idx = tid; idx < 64 * NF4; idx += THREADS) {
                const float p = u.pr[idx / NF4];
                __stcs(o4 + idx, make_float4(p, p, p, p));
            }
        }
    }
}

// ---------------------------------------------------------------------------
extern "C" void kernel_launch(void* const* d_in, const int* in_sizes, int n_in,
                              void* d_out, int out_size)
{
    const float* a = (const float*)d_in[0];
    const float* b = (const float*)d_in[1];
    float* out = (float*)d_out;

    reset_kernel<<<1, 256>>>();
    persistent_kernel<<<GRID, THREADS>>>(a, b, out);
}

// round 6
// speedup vs baseline: 1.0802x; 1.0802x over previous
#include <cuda_runtime.h>
#include <cstdint>

// CosineSim3D — cp.async-pipelined 3-kernel version.
//   K1: g_part4[item] = partial sum of normalized b rows (256-row slices)
//   K2: fold 4 partials -> s_b ; score a rows -> g_scores
//   K3: per-CTA redundant softmax + broadcast write (unchanged from R4)
//
// a, b : [128, 1024, 300] fp32   out : [128, 1024, 300] fp32

#define BATCH   128
#define NROWS   1024
#define DIM     300
#define NF4     75
#define EPSV    1e-7f

#define TROWS   32
#define TILE_B  (TROWS * DIM * 4)      // 38400 B per tile
#define NSLICE  4                      // 256-row slices per batch
#define SROWS   (NROWS / NSLICE)       // 256
#define NTILES  (SROWS / TROWS)        // 8
#define NITEMS  (BATCH * NSLICE)       // 512 work items
#define PGRID   296                    // 148 SMs x 2 resident CTAs
#define SMEMB   (2 * TILE_B)           // 76800 B (2-stage pipeline)

// scratch (no cudaMalloc allowed)
__device__ float4 g_part4[NITEMS * NF4];
__device__ float  g_scores[BATCH * NROWS];
__device__ int    g_ticket[2];

__device__ __forceinline__ float dot4(float4 x, float4 y) {
    return x.x * y.x + x.y * y.y + x.z * y.z + x.w * y.w;
}
__device__ __forceinline__ void fma4(float4& a, float4 v, float s) {
    a.x += v.x * s; a.y += v.y * s; a.z += v.z * s; a.w += v.w * s;
}
__device__ __forceinline__ void add4(float4& a, float4 v) {
    a.x += v.x; a.y += v.y; a.z += v.z; a.w += v.w;
}

__device__ __forceinline__ void cp_async16(uint32_t saddr, const void* gptr) {
    asm volatile("cp.async.cg.shared.global [%0], [%1], 16;"
                 :: "r"(saddr), "l"(gptr) : "memory");
}
#define CP_COMMIT() asm volatile("cp.async.commit_group;" ::: "memory")
#define CP_WAIT0()  asm volatile("cp.async.wait_group 0;" ::: "memory")
#define CP_WAIT1()  asm volatile("cp.async.wait_group 1;" ::: "memory")

// 38400 B = 2400 x 16 B with 256 threads (9 full rounds + 96)
__device__ __forceinline__ void load_tile(uint32_t sdst, const char* gsrc, int tid) {
#pragma unroll
    for (int i = 0; i < 9; i++)
        cp_async16(sdst + (tid + i * 256) * 16, gsrc + (size_t)(tid + i * 256) * 16);
    if (tid < 96)
        cp_async16(sdst + (tid + 2304) * 16, gsrc + (size_t)(tid + 2304) * 16);
}

__global__ void reset_kernel() {
    if (threadIdx.x < 2) g_ticket[threadIdx.x] = 0;
}

// ---------------------------------------------------------------------------
// K1: normalized-b partial sums, cp.async pipelined.
// ---------------------------------------------------------------------------
__global__ __launch_bounds__(256, 2) void k1_bnorm(const float* __restrict__ b)
{
    extern __shared__ char dsm[];
    __shared__ int sh_i;
    const int tid = threadIdx.x, warp = tid >> 5, lane = tid & 31;
    const float4 z4 = make_float4(0.f, 0.f, 0.f, 0.f);
    const uint32_t sb = (uint32_t)__cvta_generic_to_shared(dsm);

    for (;;) {
        __syncthreads();                      // protect dsm reuse across items
        if (tid == 0) sh_i = atomicAdd(&g_ticket[0], 1);
        __syncthreads();
        const int item = sh_i;
        if (item >= NITEMS) break;
        const int k = item >> 2, s = item & 3;
        const char* src = (const char*)(b + ((size_t)k * NROWS + s * SROWS) * DIM);

        load_tile(sb, src, tid);
        CP_COMMIT();

        float4 acc0 = z4, acc1 = z4, acc2 = z4;
        for (int t = 0; t < NTILES; t++) {
            if (t + 1 < NTILES) {
                load_tile(sb + ((t + 1) & 1) * TILE_B,
                          src + (size_t)(t + 1) * TILE_B, tid);
                CP_COMMIT();
                CP_WAIT1();                   // tile t arrived
            } else {
                CP_WAIT0();
            }
            __syncthreads();

            const char* tile = dsm + (t & 1) * TILE_B;
#pragma unroll
            for (int i = 0; i < 4; i++) {
                const float4* row = (const float4*)(tile + (warp * 4 + i) * (DIM * 4));
                const float4 v0 = row[lane];
                const float4 v1 = row[lane + 32];
                const float4 v2 = (lane < NF4 - 64) ? row[lane + 64] : z4;
                float ss = dot4(v0, v0) + dot4(v1, v1) + dot4(v2, v2);
#pragma unroll
                for (int o = 16; o > 0; o >>= 1)
                    ss += __shfl_xor_sync(0xffffffffu, ss, o);
                const float inv = rsqrtf(fmaxf(ss, EPSV));
                fma4(acc0, v0, inv); fma4(acc1, v1, inv); fma4(acc2, v2, inv);
            }
            __syncthreads();                  // done reading before overwrite
        }

        // cross-warp reduce (reuse stage-0 smem; all copies drained)
        float4* sw = (float4*)dsm;            // [8][NF4+1]
        sw[warp * (NF4 + 1) + lane]      = acc0;
        sw[warp * (NF4 + 1) + lane + 32] = acc1;
        if (lane < NF4 - 64) sw[warp * (NF4 + 1) + lane + 64] = acc2;
        __syncthreads();
        if (tid < NF4) {
            float4 t = sw[tid];
#pragma unroll
            for (int w = 1; w < 8; w++) add4(t, sw[w * (NF4 + 1) + tid]);
            g_part4[item * NF4 + tid] = t;
        }
    }
}

// ---------------------------------------------------------------------------
// K2: fold partials -> s_b ; score a rows, cp.async pipelined.
// ---------------------------------------------------------------------------
__global__ __launch_bounds__(256, 2) void k2_score(const float* __restrict__ a)
{
    extern __shared__ char dsm[];
    __shared__ int sh_i;
    __shared__ float4 ssh[NF4];
    const int tid = threadIdx.x, warp = tid >> 5, lane = tid & 31;
    const float4 z4 = make_float4(0.f, 0.f, 0.f, 0.f);
    const uint32_t sb = (uint32_t)__cvta_generic_to_shared(dsm);

    for (;;) {
        __syncthreads();                      // protect dsm / ssh across items
        if (tid == 0) sh_i = atomicAdd(&g_ticket[1], 1);
        __syncthreads();
        const int item = sh_i;
        if (item >= NITEMS) break;
        const int k = item >> 2, s = item & 3;
        const char* src = (const char*)(a + ((size_t)k * NROWS + s * SROWS) * DIM);

        load_tile(sb, src, tid);
        CP_COMMIT();

        // fold 4 partials -> s_b (L2-resident, fixed order)
        if (tid < NF4) {
            float4 t = g_part4[(k * 4 + 0) * NF4 + tid];
            add4(t, g_part4[(k * 4 + 1) * NF4 + tid]);
            add4(t, g_part4[(k * 4 + 2) * NF4 + tid]);
            add4(t, g_part4[(k * 4 + 3) * NF4 + tid]);
            ssh[tid] = t;
        }
        __syncthreads();
        const float4 s0 = ssh[lane];
        const float4 s1 = ssh[lane + 32];
        const float4 s2 = (lane < NF4 - 64) ? ssh[lane + 64] : z4;

        float* sc = g_scores + k * NROWS + s * SROWS;

        for (int t = 0; t < NTILES; t++) {
            if (t + 1 < NTILES) {
                load_tile(sb + ((t + 1) & 1) * TILE_B,
                          src + (size_t)(t + 1) * TILE_B, tid);
                CP_COMMIT();
                CP_WAIT1();
            } else {
                CP_WAIT0();
            }
            __syncthreads();

            const char* tile = dsm + (t & 1) * TILE_B;
#pragma unroll
            for (int i = 0; i < 4; i++) {
                const int r = warp * 4 + i;
                const float4* row = (const float4*)(tile + r * (DIM * 4));
                const float4 v0 = row[lane];
                const float4 v1 = row[lane + 32];
                const float4 v2 = (lane < NF4 - 64) ? row[lane + 64] : z4;
                float dot = dot4(v0, s0) + dot4(v1, s1) + dot4(v2, s2);
                float ss  = dot4(v0, v0) + dot4(v1, v1) + dot4(v2, v2);
#pragma unroll
                for (int o = 16; o > 0; o >>= 1) {
                    dot += __shfl_xor_sync(0xffffffffu, dot, o);
                    ss  += __shfl_xor_sync(0xffffffffu, ss,  o);
                }
                if (lane == 0)
                    sc[t * TROWS + r] = dot * rsqrtf(fmaxf(ss, EPSV));
            }
            __syncthreads();
        }
    }
}

// ---------------------------------------------------------------------------
// K3: redundant per-CTA softmax + slice write (verbatim from R4).
// grid = 1024 (batch*8), block = 1024
// ---------------------------------------------------------------------------
__global__ __launch_bounds__(1024) void softmax_write_kernel(float* __restrict__ out)
{
    const int batch = blockIdx.x >> 3;
    const int sub   = blockIdx.x & 7;
    const int warp  = threadIdx.x >> 5;
    const int lane  = threadIdx.x & 31;

    __shared__ float probs[NROWS];
    __shared__ float red[32];

    const float x = __ldg(g_scores + batch * NROWS + threadIdx.x);

    float m = x;
#pragma unroll
    for (int o = 16; o > 0; o >>= 1)
        m = fmaxf(m, __shfl_xor_sync(0xffffffffu, m, o));
    if (lane == 0) red[warp] = m;
    __syncthreads();
    if (warp == 0) {
        float t = red[lane];
#pragma unroll
        for (int o = 16; o > 0; o >>= 1)
            t = fmaxf(t, __shfl_xor_sync(0xffffffffu, t, o));
        if (lane == 0) red[0] = t;
    }
    __syncthreads();
    const float M = red[0];

    const float e = __expf(x - M);

    float sum = e;
#pragma unroll
    for (int o = 16; o > 0; o >>= 1)
        sum += __shfl_xor_sync(0xffffffffu, sum, o);
    __syncthreads();
    if (lane == 0) red[warp] = sum;
    __syncthreads();
    if (warp == 0) {
        float t = red[lane];
#pragma unroll
        for (int o = 16; o > 0; o >>= 1)
            t += __shfl_xor_sync(0xffffffffu, t, o);
        if (lane == 0) red[0] = t;
    }
    __syncthreads();

    probs[threadIdx.x] = e * __frcp_rn(red[0]);
    __syncthreads();

    float4* o4 = reinterpret_cast<float4*>(out)
               + (size_t)batch * NROWS * NF4 + sub * 128 * NF4;
    const int rbase = sub * 128;
#pragma unroll 2
    for (int i = threadIdx.x; i < 128 * NF4; i += 1024) {
        const float p = probs[rbase + i / NF4];
        o4[i] = make_float4(p, p, p, p);
    }
}

// ---------------------------------------------------------------------------
extern "C" void kernel_launch(void* const* d_in, const int* in_sizes, int n_in,
                              void* d_out, int out_size)
{
    const float* a = (const float*)d_in[0];
    const float* b = (const float*)d_in[1];
    float* out = (float*)d_out;

    cudaFuncSetAttribute(k1_bnorm, cudaFuncAttributeMaxDynamicSharedMemorySize, SMEMB);
    cudaFuncSetAttribute(k2_score, cudaFuncAttributeMaxDynamicSharedMemorySize, SMEMB);

    reset_kernel<<<1, 32>>>();
    k1_bnorm<<<PGRID, 256, SMEMB>>>(b);
    k2_score<<<PGRID, 256, SMEMB>>>(a);
    softmax_write_kernel<<<BATCH * 8, 1024>>>(out);
}

// round 7
// speedup vs baseline: 1.1002x; 1.0185x over previous
#include <cuda_runtime.h>

// CosineSim3D factorized — 2 kernels:
//   K1: g_part4[b][p][:] = partial sums of normalized b rows (8 per batch)
//   K2 (per batch): fold partials -> s_b, score a rows (float4),
//       softmax, broadcast-write out. Mixed read+write stream.
//
// a, b : [128, 1024, 300] fp32   out : [128, 1024, 300] fp32

#define BATCH   128
#define NROWS   1024
#define DIM     300
#define NF4     75
#define EPSV    1e-7f

// scratch (no cudaMalloc allowed)
__device__ float4 g_part4[BATCH * 8 * NF4];

__device__ __forceinline__ float dot4(float4 x, float4 y) {
    return x.x * y.x + x.y * y.y + x.z * y.z + x.w * y.w;
}
__device__ __forceinline__ void fma4(float4& a, float4 v, float s) {
    a.x += v.x * s; a.y += v.y * s; a.z += v.z * s; a.w += v.w * s;
}
__device__ __forceinline__ void add4(float4& a, float4 v) {
    a.x += v.x; a.y += v.y; a.z += v.z; a.w += v.w;
}

// ---------------------------------------------------------------------------
// K1: partial normalized-b sums, 2-row ILP.
// grid = 1024 (batch*8, 128-row slices), block = 256 (8 warps x 16 rows)
// ---------------------------------------------------------------------------
__global__ __launch_bounds__(256) void partial_b_kernel(const float* __restrict__ b)
{
    const int batch = blockIdx.x >> 3;
    const int sub   = blockIdx.x & 7;
    const int warp  = threadIdx.x >> 5;
    const int lane  = threadIdx.x & 31;

    const float4 z4 = make_float4(0.f, 0.f, 0.f, 0.f);
    const float4* b4 = reinterpret_cast<const float4*>(b)
                     + ((size_t)batch * NROWS + sub * 128) * NF4;

    float4 acc0 = z4, acc1 = z4, acc2 = z4;

    // warp handles rows {warp*2, warp*2+1} + 16*i  (i = 0..7), 2 rows per iter
#pragma unroll 2
    for (int i = 0; i < 8; i++) {
        const float4* rowA = b4 + (warp * 2 + 16 * i) * NF4;
        const float4* rowB = rowA + NF4;
        const float4 A0 = __ldg(rowA + lane);
        const float4 A1 = __ldg(rowA + lane + 32);
        const float4 B0 = __ldg(rowB + lane);
        const float4 B1 = __ldg(rowB + lane + 32);
        const float4 A2 = (lane < NF4 - 64) ? __ldg(rowA + lane + 64) : z4;
        const float4 B2 = (lane < NF4 - 64) ? __ldg(rowB + lane + 64) : z4;

        float sA = dot4(A0, A0) + dot4(A1, A1) + dot4(A2, A2);
        float sB = dot4(B0, B0) + dot4(B1, B1) + dot4(B2, B2);
#pragma unroll
        for (int o = 16; o > 0; o >>= 1) {
            sA += __shfl_xor_sync(0xffffffffu, sA, o);
            sB += __shfl_xor_sync(0xffffffffu, sB, o);
        }
        const float iA = rsqrtf(fmaxf(sA, EPSV));
        const float iB = rsqrtf(fmaxf(sB, EPSV));
        fma4(acc0, A0, iA); fma4(acc0, B0, iB);
        fma4(acc1, A1, iA); fma4(acc1, B1, iB);
        fma4(acc2, A2, iA); fma4(acc2, B2, iB);
    }

    __shared__ float4 sw4[8][NF4 + 1];
    sw4[warp][lane]      = acc0;
    sw4[warp][lane + 32] = acc1;
    if (lane < NF4 - 64) sw4[warp][lane + 64] = acc2;
    __syncthreads();

    if (threadIdx.x < NF4) {
        float4 t = sw4[0][threadIdx.x];
#pragma unroll
        for (int w = 1; w < 8; w++) add4(t, sw4[w][threadIdx.x]);
        g_part4[(batch * 8 + sub) * NF4 + threadIdx.x] = t;
    }
}

// ---------------------------------------------------------------------------
// K2: per-batch fused score + softmax + broadcast write.
// grid = 128 (batch), block = 1024 (32 warps)
// ---------------------------------------------------------------------------
__global__ __launch_bounds__(1024, 1) void fused_ssw_kernel(
    const float* __restrict__ a, float* __restrict__ out)
{
    const int batch = blockIdx.x;
    const int warp  = threadIdx.x >> 5;
    const int lane  = threadIdx.x & 31;

    __shared__ float4 ssh4[NF4];
    __shared__ float  probs[NROWS];
    __shared__ float  red[32];

    const float4 z4 = make_float4(0.f, 0.f, 0.f, 0.f);

    // fold 8 partials -> s_b (L2-resident, fixed order)
    if (threadIdx.x < NF4) {
        const float4* part = g_part4 + batch * 8 * NF4;
        float4 t = part[threadIdx.x];
#pragma unroll
        for (int p = 1; p < 8; p++) add4(t, part[p * NF4 + threadIdx.x]);
        ssh4[threadIdx.x] = t;
    }
    __syncthreads();

    const float4 s0 = ssh4[lane];
    const float4 s1 = ssh4[lane + 32];
    const float4 s2 = (lane < NF4 - 64) ? ssh4[lane + 64] : z4;

    const float4* a4 = reinterpret_cast<const float4*>(a)
                     + (size_t)batch * NROWS * NF4;

    // scores: warp-per-row, 2 rows per iter (rows warp+64i, warp+64i+32)
#pragma unroll 2
    for (int i = 0; i < 16; i++) {
        const int rA = warp + 64 * i;
        const float4* rowA = a4 + rA * NF4;
        const float4* rowB = rowA + 32 * NF4;
        const float4 A0 = __ldg(rowA + lane);
        const float4 A1 = __ldg(rowA + lane + 32);
        const float4 B0 = __ldg(rowB + lane);
        const float4 B1 = __ldg(rowB + lane + 32);
        const float4 A2 = (lane < NF4 - 64) ? __ldg(rowA + lane + 64) : z4;
        const float4 B2 = (lane < NF4 - 64) ? __ldg(rowB + lane + 64) : z4;

        float dA = dot4(A0, s0) + dot4(A1, s1) + dot4(A2, s2);
        float nA = dot4(A0, A0) + dot4(A1, A1) + dot4(A2, A2);
        float dB = dot4(B0, s0) + dot4(B1, s1) + dot4(B2, s2);
        float nB = dot4(B0, B0) + dot4(B1, B1) + dot4(B2, B2);
#pragma unroll
        for (int o = 16; o > 0; o >>= 1) {
            dA += __shfl_xor_sync(0xffffffffu, dA, o);
            nA += __shfl_xor_sync(0xffffffffu, nA, o);
            dB += __shfl_xor_sync(0xffffffffu, dB, o);
            nB += __shfl_xor_sync(0xffffffffu, nB, o);
        }
        if (lane == 0) {
            probs[rA]      = dA * rsqrtf(fmaxf(nA, EPSV));
            probs[rA + 32] = dB * rsqrtf(fmaxf(nB, EPSV));
        }
    }
    __syncthreads();

    // softmax over 1024 scores (thread t owns element t)
    const float x = probs[threadIdx.x];

    float m = x;
#pragma unroll
    for (int o = 16; o > 0; o >>= 1)
        m = fmaxf(m, __shfl_xor_sync(0xffffffffu, m, o));
    if (lane == 0) red[warp] = m;
    __syncthreads();
    if (warp == 0) {
        float t = red[lane];
#pragma unroll
        for (int o = 16; o > 0; o >>= 1)
            t = fmaxf(t, __shfl_xor_sync(0xffffffffu, t, o));
        if (lane == 0) red[0] = t;
    }
    __syncthreads();
    const float M = red[0];

    const float e = __expf(x - M);

    float sum = e;
#pragma unroll
    for (int o = 16; o > 0; o >>= 1)
        sum += __shfl_xor_sync(0xffffffffu, sum, o);
    __syncthreads();                  // red[] reuse barrier
    if (lane == 0) red[warp] = sum;
    __syncthreads();
    if (warp == 0) {
        float t = red[lane];
#pragma unroll
        for (int o = 16; o > 0; o >>= 1)
            t += __shfl_xor_sync(0xffffffffu, t, o);
        if (lane == 0) red[0] = t;
    }
    __syncthreads();

    probs[threadIdx.x] = e * __frcp_rn(red[0]);
    __syncthreads();

    // broadcast write: warp-per-row (no integer division in the hot loop)
    float4* o4 = reinterpret_cast<float4*>(out) + (size_t)batch * NROWS * NF4;
#pragma unroll 4
    for (int r = warp; r < NROWS; r += 32) {
        const float p = probs[r];
        const float4 pv = make_float4(p, p, p, p);
        float4* row = o4 + r * NF4;
        row[lane]      = pv;
        row[lane + 32] = pv;
        if (lane < NF4 - 64) row[lane + 64] = pv;
    }
}

// ---------------------------------------------------------------------------
extern "C" void kernel_launch(void* const* d_in, const int* in_sizes, int n_in,
                              void* d_out, int out_size)
{
    const float* a = (const float*)d_in[0];
    const float* b = (const float*)d_in[1];
    float* out = (float*)d_out;

    partial_b_kernel<<<BATCH * 8, 256>>>(b);
    fused_ssw_kernel<<<BATCH, 1024>>>(a, out);
}